// round 10
// baseline (speedup 1.0000x reference)
#include <cuda_runtime.h>
#include <math.h>

#define HD   512      // hidden
#define ID   768      // input
#define BB   32       // batch
#define TT   512      // time
#define G4   2048     // 4*HD

// ---------------- f32x2 packed helpers (Blackwell FFMA2) ----------------
__device__ __forceinline__ void ffma2(unsigned long long& d,
                                      unsigned long long a,
                                      unsigned long long b) {
    asm("fma.rn.f32x2 %0, %1, %2, %0;" : "+l"(d) : "l"(a), "l"(b));
}
__device__ __forceinline__ unsigned long long pack2(float lo, float hi) {
    unsigned long long r;
    asm("mov.b64 %0, {%1, %2};" : "=l"(r) : "f"(lo), "f"(hi));
    return r;
}
__device__ __forceinline__ void unpack2(unsigned long long v, float& lo, float& hi) {
    asm("mov.b64 {%0, %1}, %2;" : "=f"(lo), "=f"(hi) : "l"(v));
}

// ---------------- scratch (static device memory; no allocs) ----------------
// h layout: [buf][k>>2][b][k&3] -> LDG.128 per 4 k at lane-stride 16B (nL=4)
__device__ float    g_hq[2][HD / 4][BB][4];
__device__ unsigned g_bar_count;                  // monotonic arrivals

// ---------------- init: reset barrier, seed h with h0[dir=0] ----------------
__global__ void init_kernel(const float* __restrict__ h0)
{
    int idx = blockIdx.x * blockDim.x + threadIdx.x;
    if (idx == 0) g_bar_count = 0;
    if (idx < BB * HD) {
        int b = idx >> 9;          // /HD
        int k = idx & (HD - 1);
        g_hq[0][k >> 2][b][k & 3] = h0[idx];
    }
}

// ---------------- backward direction: ONE cell step (unchanged) ----------------
__global__ __launch_bounds__(256) void lstm_bwd_step_kernel(
    const float* __restrict__ x,
    const float* __restrict__ h0,
    const float* __restrict__ c0,
    const float* __restrict__ w_ih,
    const float* __restrict__ w_hh,
    const float* __restrict__ b_ih,
    const float* __restrict__ b_hh,
    float* __restrict__ out)
{
    int tid = threadIdx.x;
    int b = tid & 31;
    int j = blockIdx.x * 8 + (tid >> 5);

    float acc[4] = {0.f, 0.f, 0.f, 0.f};
    const float* xrow = x + ((size_t)b * TT + (TT - 1)) * ID;
    #pragma unroll 4
    for (int k = 0; k < ID; k++) {
        float xv = xrow[k];
        #pragma unroll
        for (int g = 0; g < 4; g++)
            acc[g] += xv * w_ih[(size_t)(g * HD + j) * ID + k];
    }
    const float* hrow = h0 + BB * HD + (size_t)b * HD;
    #pragma unroll 4
    for (int k = 0; k < HD; k++) {
        float hv = hrow[k];
        #pragma unroll
        for (int g = 0; g < 4; g++)
            acc[g] += hv * w_hh[(size_t)(g * HD + j) * HD + k];
    }
    #pragma unroll
    for (int g = 0; g < 4; g++) acc[g] += b_ih[g * HD + j] + b_hh[g * HD + j];

    float ig = 1.f / (1.f + __expf(-acc[0]));
    float fg = 1.f / (1.f + __expf(-acc[1]));
    float gg = tanhf(acc[2]);
    float og = 1.f / (1.f + __expf(-acc[3]));
    float c  = fg * c0[BB * HD + (size_t)b * HD + j] + ig * gg;
    float h  = og * tanhf(c);
    out[b * 1024 + 512 + j] = fmaxf(h, 0.f);
}

// ---------------- fused forward: recurrence + in-kernel gx production ----------------
// 128 CTAs x 512 threads. warp seg = k-segment for dots AND batch-pair {2seg,2seg+1} for gx.
// gx for step t+4 computed during step t into an 8-slot SMEM ring (no global gx buffer).
// SMEM floats: w_hh slice 16x512, w_ih slice 16x768, partials 16x16x32, ring 8x512, bias 16(+pad)
#define SM_WHH   0
#define SM_WIH   (16*512)
#define SM_PART  (SM_WIH + 16*768)
#define SM_RING  (SM_PART + 16*16*32)
#define SM_BIAS  (SM_RING + 8*512)
#define SMEM_FLOATS (SM_BIAS + 32)
#define SMEM_BYTES  (SMEM_FLOATS * 4)

__device__ __forceinline__ unsigned ld_relaxed_gpu(const unsigned* p) {
    unsigned v;
    asm volatile("ld.relaxed.gpu.u32 %0, [%1];" : "=r"(v) : "l"(p));
    return v;
}
__device__ __forceinline__ void fence_acqrel_gpu() {
    asm volatile("fence.acq_rel.gpu;" ::: "memory");
}
__device__ __forceinline__ void red_add_relaxed_gpu(unsigned* p, unsigned v) {
    asm volatile("red.relaxed.gpu.global.add.u32 [%0], %1;" :: "l"(p), "r"(v));
}

__device__ __forceinline__ float fsig(float x) {
    return __fdividef(1.f, 1.f + __expf(-x));
}
__device__ __forceinline__ float ftanh(float x) {
    return __fdividef(2.f, 1.f + __expf(-2.f * x)) - 1.f;
}

// dots: load h (global, dense), 16 rows x 32 k, write partials
__device__ __forceinline__ void dots_phase(const float* __restrict__ wseg,
                                           float* __restrict__ part,
                                           int cur, int seg, int lane) {
    const float4* hsrc = (const float4*)g_hq[cur] + seg * 8 * 32 + lane;
    float4 h4[8];
    #pragma unroll
    for (int i = 0; i < 8; i++)
        h4[i] = __ldcg(hsrc + i * 32);

    unsigned long long acc[16];
    #pragma unroll
    for (int r = 0; r < 16; r++) acc[r] = 0ull;

    #pragma unroll
    for (int it = 0; it < 8; it++) {
        int k = it * 4;
        unsigned long long ha = pack2(h4[it].x, h4[it].y);
        unsigned long long hb = pack2(h4[it].z, h4[it].w);
        #pragma unroll
        for (int r = 0; r < 16; r++) {
            ulonglong2 w2 = *(const ulonglong2*)(wseg + r * HD + k);
            ffma2(acc[r], w2.x, ha);
            ffma2(acc[r], w2.y, hb);
        }
    }
    #pragma unroll
    for (int r = 0; r < 16; r++) {
        float lo, hi;
        unpack2(acc[r], lo, hi);
        part[(seg * 16 + r) * 32 + lane] = lo + hi;
    }
}

// gx production for timestep tt: this warp computes the CTA's 16 gate-columns
// for batches {2*seg, 2*seg+1}. lane = k-chunk (coalesced x loads), shfl reduce.
__device__ __forceinline__ void gx_work(const float* __restrict__ x,
                                        const float* __restrict__ wih_s,  // [16][768]
                                        const float* __restrict__ bias_s, // [16]
                                        float* __restrict__ ring,         // [8][512]
                                        int tt, int seg, int lane)
{
    float* slot = ring + (tt & 7) * 512;
    #pragma unroll
    for (int bi = 0; bi < 2; bi++) {
        int b = seg * 2 + bi;
        const float4* xr = (const float4*)(x + ((size_t)b * TT + tt) * ID) + lane;
        unsigned long long xp[12];
        #pragma unroll
        for (int i = 0; i < 6; i++) {
            float4 v = __ldcg(xr + i * 32);
            xp[2 * i]     = pack2(v.x, v.y);
            xp[2 * i + 1] = pack2(v.z, v.w);
        }
        float p16[16];
        #pragma unroll
        for (int r = 0; r < 16; r++) {
            unsigned long long a2 = 0ull;
            const float4* wr = (const float4*)(wih_s + r * ID) + lane;
            #pragma unroll
            for (int i = 0; i < 6; i++) {
                float4 wv = wr[i * 32];
                ffma2(a2, pack2(wv.x, wv.y), xp[2 * i]);
                ffma2(a2, pack2(wv.z, wv.w), xp[2 * i + 1]);
            }
            float lo, hi;
            unpack2(a2, lo, hi);
            p16[r] = lo + hi;
        }
        #pragma unroll
        for (int off = 16; off; off >>= 1)
            #pragma unroll
            for (int r = 0; r < 16; r++)
                p16[r] += __shfl_xor_sync(0xffffffffu, p16[r], off);
        if (lane == 0) {
            #pragma unroll
            for (int r = 0; r < 16; r++)
                slot[r * 32 + b] = p16[r] + bias_s[r];
        }
    }
}

__global__ __launch_bounds__(512) void lstm_fwd_kernel(
    const float* __restrict__ x,      // [B][T][I]
    const float* __restrict__ c0,
    const float* __restrict__ w_hh,   // [2048][512]
    const float* __restrict__ w_ih,   // [2048][768]
    const float* __restrict__ b_ih,
    const float* __restrict__ b_hh,
    float* __restrict__ out)
{
    extern __shared__ float sm[];
    float* whh_s  = sm + SM_WHH;      // [16][512]   r = g*4+u
    float* wih_s  = sm + SM_WIH;      // [16][768]
    float* part   = sm + SM_PART;     // [16 seg][16 r][32 b]
    float* ring   = sm + SM_RING;     // [8][512]    slot[r*32+b]
    float* bias_s = sm + SM_BIAS;     // [16]

    int tid  = threadIdx.x;
    int bx   = blockIdx.x;       // 0..127
    int lane = tid & 31;
    int seg  = tid >> 5;         // 0..15

    // load w_hh slice: local row r -> global row (r>>2)*512 + bx*4 + (r&3)
    for (int i = tid; i < 16 * 128; i += 512) {
        int r  = i >> 7;
        int kq = i & 127;
        int col = (r >> 2) * HD + bx * 4 + (r & 3);
        *(float4*)&whh_s[r * HD + kq * 4] =
            *(const float4*)&w_hh[(size_t)col * HD + kq * 4];
    }
    // load w_ih slice: 16 rows x 768
    for (int i = tid; i < 16 * 192; i += 512) {
        int r = i / 192;
        int q = i % 192;
        int n = (r >> 2) * HD + bx * 4 + (r & 3);
        *(float4*)&wih_s[r * ID + q * 4] =
            *(const float4*)&w_ih[(size_t)n * ID + q * 4];
    }
    if (tid < 16) {
        int n = (tid >> 2) * HD + bx * 4 + (tid & 3);
        bias_s[tid] = b_ih[n] + b_hh[n];
    }
    __syncthreads();

    // prologue: gx for t = 0..3 into ring slots 0..3
    for (int tt = 0; tt < 4; tt++)
        gx_work(x, wih_s, bias_s, ring, tt, seg, lane);
    __syncthreads();

    const float* wseg = whh_s + seg * 32;

    int u = seg;                 // for tid<128: hidden-unit sub-index 0..3
    int b = lane;
    int j = bx * 4 + u;
    float c = 0.f, hv = 0.f;
    if (tid < 128) c = c0[(size_t)b * HD + j];

    for (int step = 0; step < TT; step++) {
        int cur = step & 1;

        dots_phase(wseg, part, cur, seg, lane);
        __syncthreads();

        // ---- cell update: thread (u, b), tid<128 ----
        if (tid < 128) {
            const float* slot = ring + (step & 7) * 512;
            float gate[4];
            #pragma unroll
            for (int g = 0; g < 4; g++) {
                int r = g * 4 + u;
                float s = slot[r * 32 + b];
                #pragma unroll
                for (int ss = 0; ss < 16; ss++)
                    s += part[(ss * 16 + r) * 32 + b];
                gate[g] = s;
            }
            float ig = fsig(gate[0]);
            float fg = fsig(gate[1]);
            float gg = ftanh(gate[2]);
            float og = fsig(gate[3]);
            c  = fg * c + ig * gg;
            hv = og * ftanh(c);
            g_hq[1 - cur][bx][b][u] = hv;    // coalesced: 4 lines/warp
        }

        // ---- gx for step+4 (all warps; fills sync idle time) ----
        if (step + 4 < TT)
            gx_work(x, wih_s, bias_s, ring, step + 4, seg, lane);

        __syncthreads();   // h stores + ring writes complete CTA-wide
        if (tid == 0) {
            fence_acqrel_gpu();                       // release h stores
            red_add_relaxed_gpu(&g_bar_count, 1u);    // fire-and-forget
            unsigned target = (unsigned)(step + 1) * 128u;
            if (ld_relaxed_gpu(&g_bar_count) < target) {
                while (ld_relaxed_gpu(&g_bar_count) < target) { }
            }
            fence_acqrel_gpu();                       // acquire peers' h
        }
        __syncthreads();   // release CTA into next step
    }

    if (tid < 128) out[b * 1024 + j] = fmaxf(hv, 0.f);
}

// ---------------- launch ----------------
extern "C" void kernel_launch(void* const* d_in, const int* in_sizes, int n_in,
                              void* d_out, int out_size)
{
    const float* x      = (const float*)d_in[0];
    const float* h0     = (const float*)d_in[1];
    const float* c0     = (const float*)d_in[2];
    const float* w_ih_f = (const float*)d_in[3];
    const float* w_hh_f = (const float*)d_in[4];
    const float* b_ih_f = (const float*)d_in[5];
    const float* b_hh_f = (const float*)d_in[6];
    const float* w_ih_b = (const float*)d_in[7];
    const float* w_hh_b = (const float*)d_in[8];
    const float* b_ih_b = (const float*)d_in[9];
    const float* b_hh_b = (const float*)d_in[10];
    float* out = (float*)d_out;

    cudaFuncSetAttribute(lstm_fwd_kernel,
                         cudaFuncAttributeMaxDynamicSharedMemorySize, SMEM_BYTES);

    init_kernel<<<64, 256>>>(h0);

    lstm_bwd_step_kernel<<<64, 256>>>(x, h0, c0, w_ih_b, w_hh_b, b_ih_b, b_hh_b, out);

    lstm_fwd_kernel<<<128, 512, SMEM_BYTES>>>(x, c0, w_hh_f, w_ih_f, b_ih_f, b_hh_f, out);
}

// round 11
// speedup vs baseline: 27.8940x; 27.8940x over previous
#include <cuda_runtime.h>
#include <math.h>

#define HD   512      // hidden
#define ID   768      // input
#define BB   32       // batch
#define TT   512      // time
#define G4   2048     // 4*HD

// ---------------- f32x2 packed helpers (Blackwell FFMA2) ----------------
__device__ __forceinline__ void ffma2(unsigned long long& d,
                                      unsigned long long a,
                                      unsigned long long b) {
    asm("fma.rn.f32x2 %0, %1, %2, %0;" : "+l"(d) : "l"(a), "l"(b));
}
__device__ __forceinline__ unsigned long long pack2(float lo, float hi) {
    unsigned long long r;
    asm("mov.b64 %0, {%1, %2};" : "=l"(r) : "f"(lo), "f"(hi));
    return r;
}
__device__ __forceinline__ void unpack2(unsigned long long v, float& lo, float& hi) {
    asm("mov.b64 {%0, %1}, %2;" : "=f"(lo), "=f"(hi) : "l"(v));
}

// ---------------- scratch (static device memory; no allocs) ----------------
// gx layout: [t][n][b]  (n = gate*HD + j)  -> coalesced lane=b reads in fwd
__device__ float    g_gx[(size_t)TT * G4 * BB];
// h layout: [buf][k>>2][b][k&3] -> LDG.128 per 4 k at lane-stride 16B (nL=4)
__device__ float    g_hq[2][HD / 4][BB][4];
__device__ unsigned g_bar_count;                  // monotonic arrivals (fwd barrier)
__device__ unsigned g_t_ready[128];               // GEMM brow completion counters

// ---------------- init: reset barrier+flags, seed h with h0[dir=0] ----------------
__global__ void init_kernel(const float* __restrict__ h0)
{
    int idx = blockIdx.x * blockDim.x + threadIdx.x;
    if (idx == 0) g_bar_count = 0;
    if (idx < 128) g_t_ready[idx] = 0u;
    if (idx < BB * HD) {
        int b = idx >> 9;          // /HD
        int k = idx & (HD - 1);
        g_hq[0][k >> 2][b][k & 3] = h0[idx];
    }
}

// ---------------- sync primitives ----------------
__device__ __forceinline__ unsigned ld_relaxed_gpu(const unsigned* p) {
    unsigned v;
    asm volatile("ld.relaxed.gpu.u32 %0, [%1];" : "=r"(v) : "l"(p));
    return v;
}
__device__ __forceinline__ void fence_acqrel_gpu() {
    asm volatile("fence.acq_rel.gpu;" ::: "memory");
}
__device__ __forceinline__ void red_add_relaxed_gpu(unsigned* p, unsigned v) {
    asm volatile("red.relaxed.gpu.global.add.u32 [%0], %1;" :: "l"(p), "r"(v));
}

// ---------------- gx GEMM with transposed epilogue + per-brow publish ----------------
// grid (32, 128): blockIdx.x = bcol (N tile), blockIdx.y = brow (M tile = 4 timesteps)
// -> all 32 CTAs of brow 0 are first in launch order: t=0..3 ready in wave 1.
#define BM 128
#define BN 64
#define BK 16

__global__ __launch_bounds__(256) void gx_gemm_kernel(
    const float* __restrict__ x,     // [B][T][I]
    const float* __restrict__ w,     // [2048][768]
    const float* __restrict__ b1,
    const float* __restrict__ b2)
{
    __shared__ float As[BK][BM + 4];
    __shared__ float Bs[BK][BN + 4];
    __shared__ float St[BM][BN + 1];

    int tid  = threadIdx.x;
    int bcol = blockIdx.x;   // 0..31   (N tiles)
    int brow = blockIdx.y;   // 0..127  (M tiles; m = t*32 + b, 4 t per tile)
    int ty = tid >> 4;
    int tx = tid & 15;

    unsigned long long acc2[4][4];
    #pragma unroll
    for (int i = 0; i < 4; i++)
        #pragma unroll
        for (int j = 0; j < 4; j++) acc2[i][j] = 0ull;

    for (int k0 = 0; k0 < ID; k0 += BK) {
        #pragma unroll
        for (int i = 0; i < 8; i++) {
            int e  = i * 256 + tid;
            int r  = e >> 4;
            int kk = e & 15;
            int m  = brow * BM + r;
            int b  = m & 31, t = m >> 5;
            As[kk][r] = x[((size_t)b * TT + t) * ID + k0 + kk];
        }
        #pragma unroll
        for (int i = 0; i < 4; i++) {
            int e  = i * 256 + tid;
            int n  = e >> 4;
            int kk = e & 15;
            Bs[kk][n] = w[(size_t)(bcol * BN + n) * ID + k0 + kk];
        }
        __syncthreads();

        #pragma unroll
        for (int kk = 0; kk < BK; kk++) {
            ulonglong2 av0 = *(const ulonglong2*)&As[kk][ty * 8];
            ulonglong2 av1 = *(const ulonglong2*)&As[kk][ty * 8 + 4];
            unsigned long long ap[4] = {av0.x, av0.y, av1.x, av1.y};
            float4 bv = *(const float4*)&Bs[kk][tx * 4];
            unsigned long long bsp[4];
            bsp[0] = pack2(bv.x, bv.x);
            bsp[1] = pack2(bv.y, bv.y);
            bsp[2] = pack2(bv.z, bv.z);
            bsp[3] = pack2(bv.w, bv.w);
            #pragma unroll
            for (int ip = 0; ip < 4; ip++)
                #pragma unroll
                for (int j = 0; j < 4; j++)
                    ffma2(acc2[ip][j], ap[ip], bsp[j]);
        }
        __syncthreads();
    }

    int ncol = bcol * BN + tx * 4;
    float bias[4];
    #pragma unroll
    for (int j = 0; j < 4; j++) bias[j] = b1[ncol + j] + b2[ncol + j];

    #pragma unroll
    for (int ip = 0; ip < 4; ip++) {
        float lo[4], hi[4];
        #pragma unroll
        for (int j = 0; j < 4; j++) unpack2(acc2[ip][j], lo[j], hi[j]);
        int m0 = ty * 8 + 2 * ip;
        #pragma unroll
        for (int j = 0; j < 4; j++) {
            St[m0][tx * 4 + j]     = lo[j] + bias[j];
            St[m0 + 1][tx * 4 + j] = hi[j] + bias[j];
        }
    }
    __syncthreads();

    {
        int lane = tid & 31;
        int wp   = tid >> 5;
        #pragma unroll
        for (int round = 0; round < 8; round++) {
            int pair = wp * 32 + round * 4 + (lane >> 3);
            int t_l  = pair >> 6;
            int n_l  = pair & 63;
            int b0   = (lane & 7) * 4;
            float4 v;
            v.x = St[t_l * 32 + b0 + 0][n_l];
            v.y = St[t_l * 32 + b0 + 1][n_l];
            v.z = St[t_l * 32 + b0 + 2][n_l];
            v.w = St[t_l * 32 + b0 + 3][n_l];
            size_t dst = ((size_t)(brow * 4 + t_l) * G4 + (bcol * 64 + n_l)) * BB + b0;
            *(float4*)&g_gx[dst] = v;
        }
    }

    // publish: this CTA's slice of brow is in global memory
    __syncthreads();
    if (tid == 0) {
        fence_acqrel_gpu();
        red_add_relaxed_gpu(&g_t_ready[brow], 1u);
    }
}

// ---------------- backward direction: ONE cell step (unchanged) ----------------
__global__ __launch_bounds__(256) void lstm_bwd_step_kernel(
    const float* __restrict__ x,
    const float* __restrict__ h0,
    const float* __restrict__ c0,
    const float* __restrict__ w_ih,
    const float* __restrict__ w_hh,
    const float* __restrict__ b_ih,
    const float* __restrict__ b_hh,
    float* __restrict__ out)
{
    int tid = threadIdx.x;
    int b = tid & 31;
    int j = blockIdx.x * 8 + (tid >> 5);

    float acc[4] = {0.f, 0.f, 0.f, 0.f};
    const float* xrow = x + ((size_t)b * TT + (TT - 1)) * ID;
    #pragma unroll 4
    for (int k = 0; k < ID; k++) {
        float xv = xrow[k];
        #pragma unroll
        for (int g = 0; g < 4; g++)
            acc[g] += xv * w_ih[(size_t)(g * HD + j) * ID + k];
    }
    const float* hrow = h0 + BB * HD + (size_t)b * HD;
    #pragma unroll 4
    for (int k = 0; k < HD; k++) {
        float hv = hrow[k];
        #pragma unroll
        for (int g = 0; g < 4; g++)
            acc[g] += hv * w_hh[(size_t)(g * HD + j) * HD + k];
    }
    #pragma unroll
    for (int g = 0; g < 4; g++) acc[g] += b_ih[g * HD + j] + b_hh[g * HD + j];

    float ig = 1.f / (1.f + __expf(-acc[0]));
    float fg = 1.f / (1.f + __expf(-acc[1]));
    float gg = tanhf(acc[2]);
    float og = 1.f / (1.f + __expf(-acc[3]));
    float c  = fg * c0[BB * HD + (size_t)b * HD + j] + ig * gg;
    float h  = og * tanhf(c);
    out[b * 1024 + 512 + j] = fmaxf(h, 0.f);
}

// ---------------- forward recurrence (exact R6 skeleton + gx-ready gating) ----------------
#define SMEM_FLOATS (16*512 + 16*16*32)
#define SMEM_BYTES  (SMEM_FLOATS * 4)

__device__ __forceinline__ float fsig(float x) {
    return __fdividef(1.f, 1.f + __expf(-x));
}
__device__ __forceinline__ float ftanh(float x) {
    return __fdividef(2.f, 1.f + __expf(-2.f * x)) - 1.f;
}

__global__ __launch_bounds__(512) void lstm_fwd_kernel(
    const float* __restrict__ c0,
    const float* __restrict__ w_hh,   // [2048][512]
    float* __restrict__ out)
{
    extern __shared__ float sm[];
    float* w_s  = sm;                        // [16][512]   r = g*4+u
    float* part = sm + 16 * 512;             // [16 seg][16 r][32 b]

    int tid  = threadIdx.x;
    int bx   = blockIdx.x;       // 0..127
    int lane = tid & 31;
    int seg  = tid >> 5;         // k-segment 0..15

    // load w_hh slice: local row r -> global row (r>>2)*512 + bx*4 + (r&3)
    for (int i = tid; i < 16 * 128; i += 512) {
        int r  = i >> 7;
        int kq = i & 127;
        int col = (r >> 2) * HD + bx * 4 + (r & 3);
        *(float4*)&w_s[r * HD + kq * 4] =
            *(const float4*)&w_hh[(size_t)col * HD + kq * 4];
    }

    int u = tid >> 5;            // valid for tid<128 (0..3)
    int b = lane;
    int j = bx * 4 + u;
    float c = 0.f, hv = 0.f;
    if (tid < 128) c = c0[(size_t)b * HD + j];

    const float* wseg = w_s + seg * 32;

    __syncthreads();   // w_s ready; g_hq[0] seeded by init kernel

    for (int step = 0; step < TT; step++) {
        int cur = step & 1;

        // ---- h for this warp's k-window: 8x LDG.128, dense (nL=4) ----
        const float4* hsrc = (const float4*)g_hq[cur] + seg * 8 * 32 + lane;
        float4 h4[8];
        #pragma unroll
        for (int i = 0; i < 8; i++)
            h4[i] = __ldcg(hsrc + i * 32);

        // ---- gx prefetch (gated on concurrent GEMM progress) ----
        float gxv[4];
        if (tid < 128) {
            if ((step & 3) == 0) {
                // wait for all 32 GEMM CTAs of this brow (covers t = step..step+3)
                if (ld_relaxed_gpu(&g_t_ready[step >> 2]) < 32u) {
                    while (ld_relaxed_gpu(&g_t_ready[step >> 2]) < 32u) { }
                }
                fence_acqrel_gpu();   // acquire GEMM stores
            }
            const float* gp = g_gx + ((size_t)step * G4 + j) * BB + b;
            #pragma unroll
            for (int g = 0; g < 4; g++)
                gxv[g] = __ldcg(gp + (size_t)g * HD * BB);
        }

        // ---- dots: 16 rows x 32 k, w broadcast from SMEM, h in regs ----
        unsigned long long acc[16];
        #pragma unroll
        for (int r = 0; r < 16; r++) acc[r] = 0ull;

        #pragma unroll
        for (int it = 0; it < 8; it++) {
            int k = it * 4;
            unsigned long long ha = pack2(h4[it].x, h4[it].y);
            unsigned long long hb = pack2(h4[it].z, h4[it].w);
            #pragma unroll
            for (int r = 0; r < 16; r++) {
                ulonglong2 w2 = *(const ulonglong2*)(wseg + r * HD + k);
                ffma2(acc[r], w2.x, ha);
                ffma2(acc[r], w2.y, hb);
            }
        }
        #pragma unroll
        for (int r = 0; r < 16; r++) {
            float lo, hi;
            unpack2(acc[r], lo, hi);
            part[(seg * 16 + r) * 32 + lane] = lo + hi;
        }
        __syncthreads();

        // ---- elementwise update: thread (u, b), tid<128 ----
        if (tid < 128) {
            float gate[4];
            #pragma unroll
            for (int g = 0; g < 4; g++) {
                int r = g * 4 + u;
                float s = gxv[g];
                #pragma unroll
                for (int ss = 0; ss < 16; ss++)
                    s += part[(ss * 16 + r) * 32 + b];
                gate[g] = s;
            }
            float ig = fsig(gate[0]);
            float fg = fsig(gate[1]);
            float gg = ftanh(gate[2]);
            float og = fsig(gate[3]);
            c  = fg * c + ig * gg;
            hv = og * ftanh(c);
            // h store: [j>>2][b][j&3] = [bx][b][u]  -> 4 lines/warp, coalesced
            g_hq[1 - cur][bx][b][u] = hv;

            asm volatile("bar.sync 1, 128;");   // updaters' h stores done
            if (tid == 0) {
                fence_acqrel_gpu();                       // release h stores
                red_add_relaxed_gpu(&g_bar_count, 1u);    // fire-and-forget
                unsigned target = (unsigned)(step + 1) * 128u;
                if (ld_relaxed_gpu(&g_bar_count) < target) {
                    while (ld_relaxed_gpu(&g_bar_count) < target) { }
                }
                fence_acqrel_gpu();                       // acquire peers' h
            }
        }
        __syncthreads();   // release whole CTA into next step
    }

    if (tid < 128) out[b * 1024 + j] = fmaxf(hv, 0.f);
}

// ---------------- launch: fork GEMM+bwd onto a side stream, overlap with fwd ----------------
static cudaStream_t s_side = 0;
static cudaEvent_t  s_fork = 0, s_join = 0;

extern "C" void kernel_launch(void* const* d_in, const int* in_sizes, int n_in,
                              void* d_out, int out_size)
{
    const float* x      = (const float*)d_in[0];
    const float* h0     = (const float*)d_in[1];
    const float* c0     = (const float*)d_in[2];
    const float* w_ih_f = (const float*)d_in[3];
    const float* w_hh_f = (const float*)d_in[4];
    const float* b_ih_f = (const float*)d_in[5];
    const float* b_hh_f = (const float*)d_in[6];
    const float* w_ih_b = (const float*)d_in[7];
    const float* w_hh_b = (const float*)d_in[8];
    const float* b_ih_b = (const float*)d_in[9];
    const float* b_hh_b = (const float*)d_in[10];
    float* out = (float*)d_out;

    if (s_side == 0) {   // one-time handle creation (first call = correctness run, pre-capture)
        cudaStreamCreateWithFlags(&s_side, cudaStreamNonBlocking);
        cudaEventCreateWithFlags(&s_fork, cudaEventDisableTiming);
        cudaEventCreateWithFlags(&s_join, cudaEventDisableTiming);
    }

    cudaFuncSetAttribute(lstm_fwd_kernel,
                         cudaFuncAttributeMaxDynamicSharedMemorySize, SMEM_BYTES);

    // init on the main (capture) stream: zeroes barrier + ready flags, seeds h
    init_kernel<<<64, 256>>>(h0);

    // fork: side stream waits on init
    cudaEventRecord(s_fork, 0);
    cudaStreamWaitEvent(s_side, s_fork, 0);

    // side stream: gx GEMM (brow-major launch order) + backward single step
    dim3 gg(32, 128);
    gx_gemm_kernel<<<gg, 256, 0, s_side>>>(x, w_ih_f, b_ih_f, b_hh_f);
    lstm_bwd_step_kernel<<<64, 256, 0, s_side>>>(x, h0, c0, w_ih_b, w_hh_b,
                                                 b_ih_b, b_hh_b, out);

    // main stream: forward recurrence, CONCURRENT with the side stream
    // (consumes gx via g_t_ready flags; no stream dependency on the GEMM)
    lstm_fwd_kernel<<<128, 512, SMEM_BYTES>>>(c0, w_hh_f, out);

    // join: main stream completes only after side-stream work
    cudaEventRecord(s_join, s_side);
    cudaStreamWaitEvent(0, s_join, 0);
}